// round 8
// baseline (speedup 1.0000x reference)
#include <cuda_runtime.h>

// Problem constants
#define BV   8
#define CV   19
#define HWv  (512 * 1024)              // 524288 = 2^19
#define NPIX (BV * HWv)                // 4194304
#define THREADS 256
#define PIX_PER_THREAD 4
#define NBLOCKS (NPIX / (THREADS * PIX_PER_THREAD))   // 4096

// Two-level packed atomic reduction (no fences needed: each atomic's
// atomicity guarantees the observed old-value is exactly consistent).
//   Level 1: 8 slots, 512 blocks each.  slot = {count<<48 | fixedpoint_sum}
//   Level 2: 1 master, 8 slot-winners.  master = {count<<48 | fixedpoint_sum}
// Fixed-point (scale 2^22) addition is associative -> bit-deterministic
// result regardless of arrival order. Total sum < 1.4e7 * 2^22 = 5.9e13 < 2^48.
#define COUNT_ONE    (1ULL << 48)
#define VALUE_MASK   ((1ULL << 48) - 1)
#define SCALE        4194304.0         // 2^22
#define NSLOTS       8
#define BLOCKS_PER_SLOT (NBLOCKS / NSLOTS)   // 512
#define SLOT_STRIDE  32                // 32 u64 = 256 B apart (distinct LTS)

__device__ unsigned long long g_slots[NSLOTS * SLOT_STRIDE];  // zero-init
__device__ unsigned long long g_master = 0ULL;

__global__ __launch_bounds__(THREADS)
void ce_fused_kernel(const float* __restrict__ logits,
                     const int*   __restrict__ labels,
                     float*       __restrict__ out) {
    const int tid  = blockIdx.x * THREADS + threadIdx.x;
    const int base = tid * PIX_PER_THREAD;          // first pixel of this thread
    const int b    = base >> 19;                    // image index (HW = 2^19)
    const int pix  = base & (HWv - 1);              // pixel within image

    const float4* lp =
        reinterpret_cast<const float4*>(logits + (size_t)b * CV * HWv + pix);
    const int4 lab = __ldcs(reinterpret_cast<const int4*>(labels + base));

    float4 s  = make_float4(0.f, 0.f, 0.f, 0.f);
    float4 xl = make_float4(0.f, 0.f, 0.f, 0.f);

    #pragma unroll
    for (int c = 0; c < CV; ++c) {
        const float4 v = __ldcs(lp + c * (HWv / 4));   // streaming: evict-first
        s.x += __expf(v.x);
        s.y += __expf(v.y);
        s.z += __expf(v.z);
        s.w += __expf(v.w);
        if (c == lab.x) xl.x = v.x;
        if (c == lab.y) xl.y = v.y;
        if (c == lab.z) xl.z = v.z;
        if (c == lab.w) xl.w = v.w;
    }

    // nll = log(sum exp) - x_label ; zero at ignored pixels (label < 0)
    float loss = 0.f;
    loss += (lab.x >= 0) ? (__logf(s.x) - xl.x) : 0.f;
    loss += (lab.y >= 0) ? (__logf(s.y) - xl.y) : 0.f;
    loss += (lab.z >= 0) ? (__logf(s.z) - xl.z) : 0.f;
    loss += (lab.w >= 0) ? (__logf(s.w) - xl.w) : 0.f;

    // warp reduce
    #pragma unroll
    for (int o = 16; o > 0; o >>= 1)
        loss += __shfl_down_sync(0xFFFFFFFFu, loss, o);

    __shared__ float ws[THREADS / 32];
    if ((threadIdx.x & 31) == 0) ws[threadIdx.x >> 5] = loss;
    __syncthreads();

    if (threadIdx.x == 0) {
        float v = 0.f;
        #pragma unroll
        for (int w = 0; w < THREADS / 32; ++w) v += ws[w];

        // Deterministic fixed-point partial.
        const unsigned long long q =
            (unsigned long long)((double)v * SCALE);

        const int slot = (int)(blockIdx.x & (NSLOTS - 1));
        unsigned long long* sp = &g_slots[slot * SLOT_STRIDE];

        const unsigned long long old = atomicAdd(sp, COUNT_ONE + q);

        if ((old >> 48) == (unsigned long long)(BLOCKS_PER_SLOT - 1)) {
            // Slot winner: all 512 contributions for this slot are in.
            const unsigned long long slot_total = (old & VALUE_MASK) + q;
            *sp = 0ULL;   // reset for next replay (no more touches this launch)

            const unsigned long long mold =
                atomicAdd(&g_master, COUNT_ONE + slot_total);
            if ((mold >> 48) == (unsigned long long)(NSLOTS - 1)) {
                const unsigned long long total = (mold & VALUE_MASK) + slot_total;
                out[0] = (float)((double)total * (1.0 / (SCALE * (double)NPIX)));
                g_master = 0ULL;   // reset for next replay
            }
        }
    }
}

extern "C" void kernel_launch(void* const* d_in, const int* in_sizes, int n_in,
                              void* d_out, int out_size) {
    const float* logits = (const float*)d_in[0];
    const int*   labels = (const int*)d_in[1];
    // d_in[2] (smooth_labels) is dead in the reference forward — never read.
    float* out = (float*)d_out;

    ce_fused_kernel<<<NBLOCKS, THREADS>>>(logits, labels, out);
}

// round 9
// speedup vs baseline: 1.0294x; 1.0294x over previous
#include <cuda_runtime.h>

// Problem constants
#define BV   8
#define CV   19
#define HWv  (512 * 1024)              // 524288 = 2^19
#define NPIX (BV * HWv)                // 4194304
#define THREADS 256
#define PIX_PER_THREAD 4
#define NBLOCKS (NPIX / (THREADS * PIX_PER_THREAD))   // 4096

// Packed accumulator: bits [48..63] = arrived-block count, bits [0..47] =
// fixed-point loss sum (scale 2^22). A single atomicAdd updates both fields
// at once, so the block that observes count==NBLOCKS-1 in the returned old
// value is guaranteed the low bits hold every other block's partial.
// Fixed-point addition is associative -> bit-deterministic result
// regardless of block arrival order. Max sum ~1.4e7 * 2^22 = 5.9e13 < 2^48.
#define COUNT_ONE   (1ULL << 48)
#define VALUE_MASK  ((1ULL << 48) - 1)
#define SCALE       4194304.0          // 2^22

__device__ unsigned long long g_acc = 0ULL;   // reset by the winner each call

__global__ __launch_bounds__(THREADS)
void ce_fused_kernel(const float* __restrict__ logits,
                     const int*   __restrict__ labels,
                     float*       __restrict__ out) {
    const int tid  = blockIdx.x * THREADS + threadIdx.x;
    const int base = tid * PIX_PER_THREAD;          // first pixel of this thread
    const int b    = base >> 19;                    // image index (HW = 2^19)
    const int pix  = base & (HWv - 1);              // pixel within image

    const float4* lp =
        reinterpret_cast<const float4*>(logits + (size_t)b * CV * HWv + pix);
    const int4 lab = *reinterpret_cast<const int4*>(labels + base);

    float4 s  = make_float4(0.f, 0.f, 0.f, 0.f);
    float4 xl = make_float4(0.f, 0.f, 0.f, 0.f);

    #pragma unroll
    for (int c = 0; c < CV; ++c) {
        const float4 v = lp[c * (HWv / 4)];   // default-cached LDG (no .cs)
        s.x += __expf(v.x);
        s.y += __expf(v.y);
        s.z += __expf(v.z);
        s.w += __expf(v.w);
        if (c == lab.x) xl.x = v.x;
        if (c == lab.y) xl.y = v.y;
        if (c == lab.z) xl.z = v.z;
        if (c == lab.w) xl.w = v.w;
    }

    // nll = log(sum exp) - x_label ; zero at ignored pixels (label < 0)
    float loss = 0.f;
    loss += (lab.x >= 0) ? (__logf(s.x) - xl.x) : 0.f;
    loss += (lab.y >= 0) ? (__logf(s.y) - xl.y) : 0.f;
    loss += (lab.z >= 0) ? (__logf(s.z) - xl.z) : 0.f;
    loss += (lab.w >= 0) ? (__logf(s.w) - xl.w) : 0.f;

    // warp reduce
    #pragma unroll
    for (int o = 16; o > 0; o >>= 1)
        loss += __shfl_down_sync(0xFFFFFFFFu, loss, o);

    __shared__ float ws[THREADS / 32];
    if ((threadIdx.x & 31) == 0) ws[threadIdx.x >> 5] = loss;
    __syncthreads();

    if (threadIdx.x == 0) {
        float v = 0.f;
        #pragma unroll
        for (int w = 0; w < THREADS / 32; ++w) v += ws[w];

        // Deterministic fixed-point partial.
        const unsigned long long q =
            (unsigned long long)((double)v * SCALE);

        const unsigned long long old = atomicAdd(&g_acc, COUNT_ONE + q);

        if ((old >> 48) == (unsigned long long)(NBLOCKS - 1)) {
            // Last block: old's low bits = sum of all other partials.
            const unsigned long long total = (old & VALUE_MASK) + q;
            out[0] = (float)((double)total * (1.0 / (SCALE * (double)NPIX)));
            g_acc = 0ULL;   // reset for the next graph replay
        }
    }
}

extern "C" void kernel_launch(void* const* d_in, const int* in_sizes, int n_in,
                              void* d_out, int out_size) {
    const float* logits = (const float*)d_in[0];
    const int*   labels = (const int*)d_in[1];
    // d_in[2] (smooth_labels) is dead in the reference forward — never read.
    float* out = (float*)d_out;

    ce_fused_kernel<<<NBLOCKS, THREADS>>>(logits, labels, out);
}

// round 10
// speedup vs baseline: 1.0300x; 1.0006x over previous
#include <cuda_runtime.h>

// Problem constants
#define BV   8
#define CV   19
#define HWv  (512 * 1024)              // 524288 = 2^19
#define NPIX (BV * HWv)                // 4194304
#define THREADS 256
#define PIX_PER_THREAD 4
#define NBLOCKS (NPIX / (THREADS * PIX_PER_THREAD))   // 4096

// Packed accumulator: bits [48..63] = arrived-block count, bits [0..47] =
// fixed-point loss sum (scale 2^22). One atomicAdd updates both fields, so
// the block observing count==NBLOCKS-1 in the returned old value knows the
// low bits hold every other block's partial. Fixed-point addition is
// associative -> bit-deterministic regardless of arrival order.
#define COUNT_ONE   (1ULL << 48)
#define VALUE_MASK  ((1ULL << 48) - 1)
#define SCALE       4194304.0          // 2^22

__device__ unsigned long long g_acc = 0ULL;   // reset by the winner each call

// minBlocksPerMultiprocessor=4 -> reg cap 64: lets ptxas batch many more of
// the 19 independent float4 loads in flight per thread (deep MLP), trading
// occupancy (which we have in excess) for outstanding-sector count (which
// sets achieved DRAM bandwidth).
__global__ void __launch_bounds__(THREADS, 4)
ce_fused_kernel(const float* __restrict__ logits,
                const int*   __restrict__ labels,
                float*       __restrict__ out) {
    const int tid  = blockIdx.x * THREADS + threadIdx.x;
    const int base = tid * PIX_PER_THREAD;          // first pixel of this thread
    const int b    = base >> 19;                    // image index (HW = 2^19)
    const int pix  = base & (HWv - 1);              // pixel within image

    const float4* lp =
        reinterpret_cast<const float4*>(logits + (size_t)b * CV * HWv + pix);
    const int4 lab = *reinterpret_cast<const int4*>(labels + base);

    // Phase 1: issue ALL class loads up front (independent addresses, 2 MB
    // apart, fully coalesced within the warp) -> deep MLP.
    float4 v[CV];
    #pragma unroll
    for (int c = 0; c < CV; ++c)
        v[c] = lp[c * (HWv / 4)];

    // Phase 2: compute.
    float4 s  = make_float4(0.f, 0.f, 0.f, 0.f);
    float4 xl = make_float4(0.f, 0.f, 0.f, 0.f);
    #pragma unroll
    for (int c = 0; c < CV; ++c) {
        s.x += __expf(v[c].x);
        s.y += __expf(v[c].y);
        s.z += __expf(v[c].z);
        s.w += __expf(v[c].w);
        if (c == lab.x) xl.x = v[c].x;
        if (c == lab.y) xl.y = v[c].y;
        if (c == lab.z) xl.z = v[c].z;
        if (c == lab.w) xl.w = v[c].w;
    }

    // nll = log(sum exp) - x_label ; zero at ignored pixels (label < 0)
    float loss = 0.f;
    loss += (lab.x >= 0) ? (__logf(s.x) - xl.x) : 0.f;
    loss += (lab.y >= 0) ? (__logf(s.y) - xl.y) : 0.f;
    loss += (lab.z >= 0) ? (__logf(s.z) - xl.z) : 0.f;
    loss += (lab.w >= 0) ? (__logf(s.w) - xl.w) : 0.f;

    // warp reduce
    #pragma unroll
    for (int o = 16; o > 0; o >>= 1)
        loss += __shfl_down_sync(0xFFFFFFFFu, loss, o);

    __shared__ float ws[THREADS / 32];
    if ((threadIdx.x & 31) == 0) ws[threadIdx.x >> 5] = loss;
    __syncthreads();

    if (threadIdx.x == 0) {
        float t = 0.f;
        #pragma unroll
        for (int w = 0; w < THREADS / 32; ++w) t += ws[w];

        const unsigned long long q =
            (unsigned long long)((double)t * SCALE);

        const unsigned long long old = atomicAdd(&g_acc, COUNT_ONE + q);

        if ((old >> 48) == (unsigned long long)(NBLOCKS - 1)) {
            const unsigned long long total = (old & VALUE_MASK) + q;
            out[0] = (float)((double)total * (1.0 / (SCALE * (double)NPIX)));
            g_acc = 0ULL;   // reset for the next graph replay
        }
    }
}

extern "C" void kernel_launch(void* const* d_in, const int* in_sizes, int n_in,
                              void* d_out, int out_size) {
    const float* logits = (const float*)d_in[0];
    const int*   labels = (const int*)d_in[1];
    // d_in[2] (smooth_labels) is dead in the reference forward — never read.
    float* out = (float*)d_out;

    ce_fused_kernel<<<NBLOCKS, THREADS>>>(logits, labels, out);
}